// round 1
// baseline (speedup 1.0000x reference)
#include <cuda_runtime.h>
#include <cuda_bf16.h>
#include <cstdint>

// Problem constants (match reference)
#define BATCH   8192
#define MDIM    512
#define HDIM    1024
#define ROWS    (2 * BATCH)          // anchor rows stacked on positive rows = 16384

// Scratch in device globals (no allocation allowed)
__device__ float g_X [(size_t)ROWS * MDIM];   // 32 MB  (stacked input)
__device__ float g_A0[(size_t)ROWS * HDIM];   // 64 MB
__device__ float g_A1[(size_t)ROWS * HDIM];   // 64 MB
__device__ int   g_mask_byte_flag;            // 1 = mask is uint8/bool bytes, 0 = 4-byte elems

// ---------------------------------------------------------------------------
// Mask dtype detection: scan first 64KB of the mask buffer.
//   any byte value > 1            -> 4-byte layout (float32 bit pattern)
//   any nonzero byte at off%4!=0  -> uint8 layout
//   else                          -> 4-byte layout (int32 0/1)
// ---------------------------------------------------------------------------
__global__ void detect_mask_kernel(const unsigned char* __restrict__ m) {
    __shared__ int s_gt1, s_odd;
    if (threadIdx.x == 0) { s_gt1 = 0; s_odd = 0; }
    __syncthreads();
    int gt1 = 0, odd = 0;
    for (int o = threadIdx.x; o < 65536; o += blockDim.x) {
        unsigned char b = m[o];
        if (b > 1) gt1 = 1;
        if ((o & 3) && b) odd = 1;
    }
    if (gt1) atomicOr(&s_gt1, 1);
    if (odd) atomicOr(&s_odd, 1);
    __syncthreads();
    if (threadIdx.x == 0)
        g_mask_byte_flag = (!s_gt1 && s_odd) ? 1 : 0;
}

// ---------------------------------------------------------------------------
// Build stacked input X: rows [0,B) = anchor, rows [B,2B) = where(mask, rnd, anchor)
// ---------------------------------------------------------------------------
__global__ void build_x_kernel(const float* __restrict__ anchor,
                               const float* __restrict__ rnd,
                               const void*  __restrict__ mask) {
    int i = blockIdx.x * blockDim.x + threadIdx.x;
    const int n = BATCH * MDIM;
    if (i >= n) return;
    float a = anchor[i];
    g_X[i] = a;
    bool m;
    if (g_mask_byte_flag)
        m = ((const unsigned char*)mask)[i] != 0;
    else
        m = ((const unsigned int*)mask)[i] != 0u;   // covers int32 0/1 AND float32 0.0/1.0
    g_X[(size_t)n + i] = m ? rnd[i] : a;
}

// ---------------------------------------------------------------------------
// fp32 SGEMM + bias + ReLU:  C[ROWS x N] = relu(A[ROWS x K] @ W[K x N] + bias)
// BM=BN=128, BK=16, 256 threads, 8x8 per thread, float4 loads/stores.
// All dims divide tile sizes (ROWS=16384, K in {512,1024}, N=1024) -> no guards.
// ---------------------------------------------------------------------------
__global__ void __launch_bounds__(256, 2)
sgemm_bias_relu(const float* __restrict__ A, const float* __restrict__ W,
                const float* __restrict__ bias, float* __restrict__ C,
                int K, int N) {
    constexpr int BM = 128, BN = 128, BK = 16;
    __shared__ float As[BK][BM];
    __shared__ float Bs[BK][BN];

    const int tid = threadIdx.x;
    const int tx = tid & 15;       // 0..15 -> N direction
    const int ty = tid >> 4;       // 0..15 -> M direction

    const float* Ab = A + (size_t)blockIdx.y * BM * K;
    const float* Wb = W + (size_t)blockIdx.x * BN;

    // A-tile loader: thread -> (row = tid/4 and +64, col4 = (tid%4)*4)
    const int arow  = tid >> 2;          // 0..63
    const int acol4 = (tid & 3) << 2;    // 0,4,8,12
    // B-tile loader: thread -> (row = tid/32 and +8, col4 = (tid%32)*4)
    const int brow  = tid >> 5;          // 0..7
    const int bcol4 = (tid & 31) << 2;   // 0..124

    float acc[8][8];
#pragma unroll
    for (int i = 0; i < 8; i++)
#pragma unroll
        for (int j = 0; j < 8; j++) acc[i][j] = 0.f;

    for (int k0 = 0; k0 < K; k0 += BK) {
        float4 a0 = *(const float4*)(Ab + (size_t)arow        * K + k0 + acol4);
        float4 a1 = *(const float4*)(Ab + (size_t)(arow + 64) * K + k0 + acol4);
        float4 b0 = *(const float4*)(Wb + (size_t)(k0 + brow)     * N + bcol4);
        float4 b1 = *(const float4*)(Wb + (size_t)(k0 + brow + 8) * N + bcol4);

        As[acol4 + 0][arow] = a0.x;  As[acol4 + 1][arow] = a0.y;
        As[acol4 + 2][arow] = a0.z;  As[acol4 + 3][arow] = a0.w;
        As[acol4 + 0][arow + 64] = a1.x;  As[acol4 + 1][arow + 64] = a1.y;
        As[acol4 + 2][arow + 64] = a1.z;  As[acol4 + 3][arow + 64] = a1.w;
        *(float4*)&Bs[brow][bcol4]     = b0;
        *(float4*)&Bs[brow + 8][bcol4] = b1;
        __syncthreads();

#pragma unroll
        for (int k = 0; k < BK; k++) {
            float4 ra0 = *(const float4*)&As[k][ty * 8];
            float4 ra1 = *(const float4*)&As[k][ty * 8 + 4];
            float4 rb0 = *(const float4*)&Bs[k][tx * 8];
            float4 rb1 = *(const float4*)&Bs[k][tx * 8 + 4];
            float ar[8] = {ra0.x, ra0.y, ra0.z, ra0.w, ra1.x, ra1.y, ra1.z, ra1.w};
            float br[8] = {rb0.x, rb0.y, rb0.z, rb0.w, rb1.x, rb1.y, rb1.z, rb1.w};
#pragma unroll
            for (int i = 0; i < 8; i++)
#pragma unroll
                for (int j = 0; j < 8; j++)
                    acc[i][j] += ar[i] * br[j];
        }
        __syncthreads();
    }

    // Epilogue: bias + ReLU, vectorized store
    const int row0 = blockIdx.y * BM + ty * 8;
    const int col0 = blockIdx.x * BN + tx * 8;
    float bv[8];
#pragma unroll
    for (int j = 0; j < 8; j++) bv[j] = bias[col0 + j];

#pragma unroll
    for (int i = 0; i < 8; i++) {
        float* Crow = C + (size_t)(row0 + i) * N + col0;
        float4 v0, v1;
        v0.x = fmaxf(acc[i][0] + bv[0], 0.f);
        v0.y = fmaxf(acc[i][1] + bv[1], 0.f);
        v0.z = fmaxf(acc[i][2] + bv[2], 0.f);
        v0.w = fmaxf(acc[i][3] + bv[3], 0.f);
        v1.x = fmaxf(acc[i][4] + bv[4], 0.f);
        v1.y = fmaxf(acc[i][5] + bv[5], 0.f);
        v1.z = fmaxf(acc[i][6] + bv[6], 0.f);
        v1.w = fmaxf(acc[i][7] + bv[7], 0.f);
        *(float4*)(Crow)     = v0;
        *(float4*)(Crow + 4) = v1;
    }
}

// ---------------------------------------------------------------------------
// kernel_launch: 1 detect + 1 select + 6 fused GEMM layers
// Inputs (metadata order):
//   0 anchor (B*M f32)      1 random_sample (B*M f32)   2 corruption_mask (B*M)
//   3 enc_w0 (M*H f32)      4 enc_b0 (H)                5 enc_w (3*H*H)
//   6 enc_b (3*H)           7 head_w (2*H*H)            8 head_b (2*H)
// Output: [emb_anchor (B*H) | emb_positive (B*H)] f32
// ---------------------------------------------------------------------------
extern "C" void kernel_launch(void* const* d_in, const int* in_sizes, int n_in,
                              void* d_out, int out_size) {
    const float* anchor = (const float*)d_in[0];
    const float* rnd    = (const float*)d_in[1];
    const void*  mask   = d_in[2];
    const float* enc_w0 = (const float*)d_in[3];
    const float* enc_b0 = (const float*)d_in[4];
    const float* enc_w  = (const float*)d_in[5];
    const float* enc_b  = (const float*)d_in[6];
    const float* head_w = (const float*)d_in[7];
    const float* head_b = (const float*)d_in[8];
    float* out = (float*)d_out;

    float *X, *A0, *A1;
    cudaGetSymbolAddress((void**)&X,  g_X);
    cudaGetSymbolAddress((void**)&A0, g_A0);
    cudaGetSymbolAddress((void**)&A1, g_A1);

    detect_mask_kernel<<<1, 256>>>((const unsigned char*)mask);

    const int nSel = BATCH * MDIM;
    build_x_kernel<<<(nSel + 255) / 256, 256>>>(anchor, rnd, mask);

    dim3 grid(HDIM / 128, ROWS / 128);   // (8, 128)
    dim3 blk(256);

    // L0: X(16384x512) @ enc_w0(512x1024) -> A0
    sgemm_bias_relu<<<grid, blk>>>(X,  enc_w0,                 enc_b0,            A0,  MDIM, HDIM);
    // L1..L3: enc_w[i]
    sgemm_bias_relu<<<grid, blk>>>(A0, enc_w + 0 * HDIM * HDIM, enc_b + 0 * HDIM, A1,  HDIM, HDIM);
    sgemm_bias_relu<<<grid, blk>>>(A1, enc_w + 1 * HDIM * HDIM, enc_b + 1 * HDIM, A0,  HDIM, HDIM);
    sgemm_bias_relu<<<grid, blk>>>(A0, enc_w + 2 * HDIM * HDIM, enc_b + 2 * HDIM, A1,  HDIM, HDIM);
    // L4..L5: head_w[i]; final layer writes straight to d_out
    sgemm_bias_relu<<<grid, blk>>>(A1, head_w + 0 * HDIM * HDIM, head_b + 0 * HDIM, A0, HDIM, HDIM);
    sgemm_bias_relu<<<grid, blk>>>(A0, head_w + 1 * HDIM * HDIM, head_b + 1 * HDIM, out, HDIM, HDIM);
}

// round 2
// speedup vs baseline: 1.0008x; 1.0008x over previous
#include <cuda_runtime.h>
#include <cuda_bf16.h>
#include <cstdint>

// Problem constants (match reference)
#define BATCH   8192
#define MDIM    512
#define HDIM    1024
#define ROWS    (2 * BATCH)          // anchor rows stacked on positive rows = 16384

// Scratch in device globals (no allocation allowed)
__device__ float g_X [(size_t)ROWS * MDIM];   // 32 MB  (stacked input)
__device__ float g_A0[(size_t)ROWS * HDIM];   // 64 MB
__device__ float g_A1[(size_t)ROWS * HDIM];   // 64 MB
__device__ int   g_mask_byte_flag;            // 1 = mask is uint8/bool bytes, 0 = 4-byte elems

// ---------------------------------------------------------------------------
// Mask dtype detection: scan first 64KB of the mask buffer.
//   any byte value > 1            -> 4-byte layout (float32 bit pattern)
//   any nonzero byte at off%4!=0  -> uint8 layout
//   else                          -> 4-byte layout (int32 0/1)
// ---------------------------------------------------------------------------
__global__ void detect_mask_kernel(const unsigned char* __restrict__ m) {
    __shared__ int s_gt1, s_odd;
    if (threadIdx.x == 0) { s_gt1 = 0; s_odd = 0; }
    __syncthreads();
    int gt1 = 0, odd = 0;
    for (int o = threadIdx.x; o < 65536; o += blockDim.x) {
        unsigned char b = m[o];
        if (b > 1) gt1 = 1;
        if ((o & 3) && b) odd = 1;
    }
    if (gt1) atomicOr(&s_gt1, 1);
    if (odd) atomicOr(&s_odd, 1);
    __syncthreads();
    if (threadIdx.x == 0)
        g_mask_byte_flag = (!s_gt1 && s_odd) ? 1 : 0;
}

// ---------------------------------------------------------------------------
// Build stacked input X: rows [0,B) = anchor, rows [B,2B) = where(mask, rnd, anchor)
// ---------------------------------------------------------------------------
__global__ void build_x_kernel(const float* __restrict__ anchor,
                               const float* __restrict__ rnd,
                               const void*  __restrict__ mask) {
    int i = blockIdx.x * blockDim.x + threadIdx.x;
    const int n = BATCH * MDIM;
    if (i >= n) return;
    float a = anchor[i];
    g_X[i] = a;
    bool m;
    if (g_mask_byte_flag)
        m = ((const unsigned char*)mask)[i] != 0;
    else
        m = ((const unsigned int*)mask)[i] != 0u;   // covers int32 0/1 AND float32 0.0/1.0
    g_X[(size_t)n + i] = m ? rnd[i] : a;
}

// ---------------------------------------------------------------------------
// fp32 SGEMM + bias + ReLU:  C[ROWS x N] = relu(A[ROWS x K] @ W[K x N] + bias)
// BM=BN=128, BK=16, 256 threads, 8x8 per thread, float4 loads/stores.
// All dims divide tile sizes (ROWS=16384, K in {512,1024}, N=1024) -> no guards.
// ---------------------------------------------------------------------------
__global__ void __launch_bounds__(256, 2)
sgemm_bias_relu(const float* __restrict__ A, const float* __restrict__ W,
                const float* __restrict__ bias, float* __restrict__ C,
                int K, int N) {
    constexpr int BM = 128, BN = 128, BK = 16;
    __shared__ float As[BK][BM];
    __shared__ float Bs[BK][BN];

    const int tid = threadIdx.x;
    const int tx = tid & 15;       // 0..15 -> N direction
    const int ty = tid >> 4;       // 0..15 -> M direction

    const float* Ab = A + (size_t)blockIdx.y * BM * K;
    const float* Wb = W + (size_t)blockIdx.x * BN;

    // A-tile loader: thread -> (row = tid/4 and +64, col4 = (tid%4)*4)
    const int arow  = tid >> 2;          // 0..63
    const int acol4 = (tid & 3) << 2;    // 0,4,8,12
    // B-tile loader: thread -> (row = tid/32 and +8, col4 = (tid%32)*4)
    const int brow  = tid >> 5;          // 0..7
    const int bcol4 = (tid & 31) << 2;   // 0..124

    float acc[8][8];
#pragma unroll
    for (int i = 0; i < 8; i++)
#pragma unroll
        for (int j = 0; j < 8; j++) acc[i][j] = 0.f;

    for (int k0 = 0; k0 < K; k0 += BK) {
        float4 a0 = *(const float4*)(Ab + (size_t)arow        * K + k0 + acol4);
        float4 a1 = *(const float4*)(Ab + (size_t)(arow + 64) * K + k0 + acol4);
        float4 b0 = *(const float4*)(Wb + (size_t)(k0 + brow)     * N + bcol4);
        float4 b1 = *(const float4*)(Wb + (size_t)(k0 + brow + 8) * N + bcol4);

        As[acol4 + 0][arow] = a0.x;  As[acol4 + 1][arow] = a0.y;
        As[acol4 + 2][arow] = a0.z;  As[acol4 + 3][arow] = a0.w;
        As[acol4 + 0][arow + 64] = a1.x;  As[acol4 + 1][arow + 64] = a1.y;
        As[acol4 + 2][arow + 64] = a1.z;  As[acol4 + 3][arow + 64] = a1.w;
        *(float4*)&Bs[brow][bcol4]     = b0;
        *(float4*)&Bs[brow + 8][bcol4] = b1;
        __syncthreads();

#pragma unroll
        for (int k = 0; k < BK; k++) {
            float4 ra0 = *(const float4*)&As[k][ty * 8];
            float4 ra1 = *(const float4*)&As[k][ty * 8 + 4];
            float4 rb0 = *(const float4*)&Bs[k][tx * 8];
            float4 rb1 = *(const float4*)&Bs[k][tx * 8 + 4];
            float ar[8] = {ra0.x, ra0.y, ra0.z, ra0.w, ra1.x, ra1.y, ra1.z, ra1.w};
            float br[8] = {rb0.x, rb0.y, rb0.z, rb0.w, rb1.x, rb1.y, rb1.z, rb1.w};
#pragma unroll
            for (int i = 0; i < 8; i++)
#pragma unroll
                for (int j = 0; j < 8; j++)
                    acc[i][j] += ar[i] * br[j];
        }
        __syncthreads();
    }

    // Epilogue: bias + ReLU, vectorized store
    const int row0 = blockIdx.y * BM + ty * 8;
    const int col0 = blockIdx.x * BN + tx * 8;
    float bv[8];
#pragma unroll
    for (int j = 0; j < 8; j++) bv[j] = bias[col0 + j];

#pragma unroll
    for (int i = 0; i < 8; i++) {
        float* Crow = C + (size_t)(row0 + i) * N + col0;
        float4 v0, v1;
        v0.x = fmaxf(acc[i][0] + bv[0], 0.f);
        v0.y = fmaxf(acc[i][1] + bv[1], 0.f);
        v0.z = fmaxf(acc[i][2] + bv[2], 0.f);
        v0.w = fmaxf(acc[i][3] + bv[3], 0.f);
        v1.x = fmaxf(acc[i][4] + bv[4], 0.f);
        v1.y = fmaxf(acc[i][5] + bv[5], 0.f);
        v1.z = fmaxf(acc[i][6] + bv[6], 0.f);
        v1.w = fmaxf(acc[i][7] + bv[7], 0.f);
        *(float4*)(Crow)     = v0;
        *(float4*)(Crow + 4) = v1;
    }
}

// ---------------------------------------------------------------------------
// kernel_launch: 1 detect + 1 select + 6 fused GEMM layers
// Inputs (metadata order):
//   0 anchor (B*M f32)      1 random_sample (B*M f32)   2 corruption_mask (B*M)
//   3 enc_w0 (M*H f32)      4 enc_b0 (H)                5 enc_w (3*H*H)
//   6 enc_b (3*H)           7 head_w (2*H*H)            8 head_b (2*H)
// Output: [emb_anchor (B*H) | emb_positive (B*H)] f32
// ---------------------------------------------------------------------------
extern "C" void kernel_launch(void* const* d_in, const int* in_sizes, int n_in,
                              void* d_out, int out_size) {
    const float* anchor = (const float*)d_in[0];
    const float* rnd    = (const float*)d_in[1];
    const void*  mask   = d_in[2];
    const float* enc_w0 = (const float*)d_in[3];
    const float* enc_b0 = (const float*)d_in[4];
    const float* enc_w  = (const float*)d_in[5];
    const float* enc_b  = (const float*)d_in[6];
    const float* head_w = (const float*)d_in[7];
    const float* head_b = (const float*)d_in[8];
    float* out = (float*)d_out;

    float *X, *A0, *A1;
    cudaGetSymbolAddress((void**)&X,  g_X);
    cudaGetSymbolAddress((void**)&A0, g_A0);
    cudaGetSymbolAddress((void**)&A1, g_A1);

    detect_mask_kernel<<<1, 256>>>((const unsigned char*)mask);

    const int nSel = BATCH * MDIM;
    build_x_kernel<<<(nSel + 255) / 256, 256>>>(anchor, rnd, mask);

    dim3 grid(HDIM / 128, ROWS / 128);   // (8, 128)
    dim3 blk(256);

    // L0: X(16384x512) @ enc_w0(512x1024) -> A0
    sgemm_bias_relu<<<grid, blk>>>(X,  enc_w0,                 enc_b0,            A0,  MDIM, HDIM);
    // L1..L3: enc_w[i]
    sgemm_bias_relu<<<grid, blk>>>(A0, enc_w + 0 * HDIM * HDIM, enc_b + 0 * HDIM, A1,  HDIM, HDIM);
    sgemm_bias_relu<<<grid, blk>>>(A1, enc_w + 1 * HDIM * HDIM, enc_b + 1 * HDIM, A0,  HDIM, HDIM);
    sgemm_bias_relu<<<grid, blk>>>(A0, enc_w + 2 * HDIM * HDIM, enc_b + 2 * HDIM, A1,  HDIM, HDIM);
    // L4..L5: head_w[i]; final layer writes straight to d_out
    sgemm_bias_relu<<<grid, blk>>>(A1, head_w + 0 * HDIM * HDIM, head_b + 0 * HDIM, A0, HDIM, HDIM);
    sgemm_bias_relu<<<grid, blk>>>(A0, head_w + 1 * HDIM * HDIM, head_b + 1 * HDIM, out, HDIM, HDIM);
}

// round 4
// speedup vs baseline: 2.1005x; 2.0989x over previous
#include <cuda_runtime.h>
#include <cuda_bf16.h>
#include <cstdint>

#define BATCH   8192
#define MDIM    512
#define HDIM    1024
#define ROWS    (2 * BATCH)          // 16384 stacked rows (anchor ; positive)

// ---------------------------------------------------------------------------
// Device scratch (no allocations allowed)
// ---------------------------------------------------------------------------
__device__ __align__(256) float g_X [(size_t)ROWS * MDIM];   // 32 MB stacked input
__device__ __align__(256) float g_A0[(size_t)ROWS * HDIM];   // 64 MB
__device__ __align__(256) float g_A1[(size_t)ROWS * HDIM];   // 64 MB
#define WTOTAL 5767168   // 512*1024 + 5*1024*1024
__device__ __align__(256) __nv_bfloat16 g_Whi[WTOTAL];
__device__ __align__(256) __nv_bfloat16 g_Wlo[WTOTAL];
__device__ int g_mask_byte_flag;

// ---------------------------------------------------------------------------
// Helpers (all compute_103-legal: ldmatrix / mma.sync / cp.async only)
// ---------------------------------------------------------------------------
__device__ __forceinline__ uint32_t smem_u32(const void* p) {
    uint32_t a;
    asm("{ .reg .u64 t; cvta.to.shared.u64 t, %1; cvt.u32.u64 %0, t; }" : "=r"(a) : "l"(p));
    return a;
}
__device__ __forceinline__ void ldsm_x4(uint32_t (&r)[4], uint32_t a) {
    asm volatile("ldmatrix.sync.aligned.m8n8.x4.shared.b16 {%0,%1,%2,%3}, [%4];"
                 : "=r"(r[0]), "=r"(r[1]), "=r"(r[2]), "=r"(r[3]) : "r"(a));
}
__device__ __forceinline__ void mma_bf16(float (&d)[4], const uint32_t (&a)[4],
                                         uint32_t b0, uint32_t b1) {
    asm volatile("mma.sync.aligned.m16n8k16.row.col.f32.bf16.bf16.f32 "
                 "{%0,%1,%2,%3}, {%4,%5,%6,%7}, {%8,%9}, {%0,%1,%2,%3};"
                 : "+f"(d[0]), "+f"(d[1]), "+f"(d[2]), "+f"(d[3])
                 : "r"(a[0]), "r"(a[1]), "r"(a[2]), "r"(a[3]), "r"(b0), "r"(b1));
}
#define CP_ASYNC16(dst, src) \
    asm volatile("cp.async.cg.shared.global [%0], [%1], 16;" :: "r"(dst), "l"(src))
#define CP_COMMIT()  asm volatile("cp.async.commit_group;" ::: "memory")
#define CP_WAIT0()   asm volatile("cp.async.wait_group 0;" ::: "memory")
#define SWZ128(o) ((o) ^ (((o) >> 3) & 0x70))

// ---------------------------------------------------------------------------
// Mask dtype detection + input build (as round 2, proven correct)
// ---------------------------------------------------------------------------
__global__ void detect_mask_kernel(const unsigned char* __restrict__ m) {
    __shared__ int s_gt1, s_odd;
    if (threadIdx.x == 0) { s_gt1 = 0; s_odd = 0; }
    __syncthreads();
    int gt1 = 0, odd = 0;
    for (int o = threadIdx.x; o < 65536; o += blockDim.x) {
        unsigned char b = m[o];
        if (b > 1) gt1 = 1;
        if ((o & 3) && b) odd = 1;
    }
    if (gt1) atomicOr(&s_gt1, 1);
    if (odd) atomicOr(&s_odd, 1);
    __syncthreads();
    if (threadIdx.x == 0) g_mask_byte_flag = (!s_gt1 && s_odd) ? 1 : 0;
}

__global__ void build_x_kernel(const float* __restrict__ anchor,
                               const float* __restrict__ rnd,
                               const void*  __restrict__ mask) {
    int i = blockIdx.x * blockDim.x + threadIdx.x;
    const int n = BATCH * MDIM;
    if (i >= n) return;
    float a = anchor[i];
    g_X[i] = a;
    bool m;
    if (g_mask_byte_flag) m = ((const unsigned char*)mask)[i] != 0;
    else                  m = ((const unsigned int*)mask)[i] != 0u;
    g_X[(size_t)n + i] = m ? rnd[i] : a;
}

// ---------------------------------------------------------------------------
// Weight transpose + bf16 split:  W[K,N] f32  ->  hi/lo [N,K] bf16
// ---------------------------------------------------------------------------
__global__ void wsplit_kernel(const float* __restrict__ W,
                              __nv_bfloat16* __restrict__ hi,
                              __nv_bfloat16* __restrict__ lo,
                              int K, int N) {
    __shared__ float t[32][33];
    int nb = blockIdx.x * 32, kb = blockIdx.y * 32;
    int tx = threadIdx.x, ty = threadIdx.y;   // (32, 8)
    for (int r = ty; r < 32; r += 8)
        t[r][tx] = W[(size_t)(kb + r) * N + nb + tx];
    __syncthreads();
    for (int r = ty; r < 32; r += 8) {
        float v = t[tx][r];
        __nv_bfloat16 h = __float2bfloat16(v);
        __nv_bfloat16 l = __float2bfloat16(v - __bfloat162float(h));
        size_t o = (size_t)(nb + r) * K + kb + tx;
        hi[o] = h;  lo[o] = l;
    }
}

// ---------------------------------------------------------------------------
// HMMA GEMM + bias + ReLU.
//   C[ROWS x 1024] = relu(A[ROWS x K] @ W + b), W pre-split [1024,K] bf16 hi/lo.
//   CTA 128x128, BK=64, 8 warps (warp tile 32x64), double-buffered SMEM,
//   split-bf16 3-pass accumulation on mma.sync m16n8k16.
// SMEM buffer p at p*65536: Ah(16K) Al(16K) Bh(16K) Bl(16K); total 128KB.
// ---------------------------------------------------------------------------
#define AH_OFF 0
#define AL_OFF 16384
#define BH_OFF 32768
#define BL_OFF 49152
#define BUF_STRIDE 65536
#define SM_TOTAL (2 * BUF_STRIDE)

__global__ void __launch_bounds__(256, 1)
gemm_hmma(const float* __restrict__ A,
          const __nv_bfloat16* __restrict__ Bthi,
          const __nv_bfloat16* __restrict__ Btlo,
          const float* __restrict__ bias,
          float* __restrict__ C,
          int K) {
    extern __shared__ char smem[];
    const uint32_t sb = smem_u32(smem);
    const int tid  = threadIdx.x;
    const int wid  = tid >> 5, lane = tid & 31;
    const int wm   = wid & 3;          // warp m index (4)
    const int wn   = wid >> 2;         // warp n index (2)
    const int mb   = blockIdx.y, nb = blockIdx.x;

    const float* Ab = A + (size_t)mb * 128 * K;
    const __nv_bfloat16* Bh = Bthi + (size_t)nb * 128 * K;
    const __nv_bfloat16* Bl = Btlo + (size_t)nb * 128 * K;

    // per-thread loader indices: seg = tid + 256*j, j<4
    //   row = seg>>3 (0..127), g = seg&7 (16B group within 128B row)
    const int lrow[4] = { (tid + 0) >> 3, (tid + 256) >> 3, (tid + 512) >> 3, (tid + 768) >> 3 };
    const int lg  [4] = { tid & 7, tid & 7, tid & 7, tid & 7 };

    float acc[2][8][4];
#pragma unroll
    for (int mt = 0; mt < 2; mt++)
#pragma unroll
        for (int nt = 0; nt < 8; nt++)
#pragma unroll
            for (int q = 0; q < 4; q++) acc[mt][nt][q] = 0.f;

    const int nchunks = K >> 6;

    // ---- prologue: chunk 0 into buffer 0 ----
    {
#pragma unroll
        for (int j = 0; j < 4; j++) {
            uint32_t sw = SWZ128((uint32_t)(lrow[j] * 128 + lg[j] * 16));
            const char* bsrc = (const char*)(Bh + (size_t)lrow[j] * K + lg[j] * 8);
            const char* lsrc = (const char*)(Bl + (size_t)lrow[j] * K + lg[j] * 8);
            CP_ASYNC16(sb + BH_OFF + sw, bsrc);
            CP_ASYNC16(sb + BL_OFF + sw, lsrc);
        }
        CP_COMMIT();
#pragma unroll
        for (int j = 0; j < 4; j++) {
            const float4* ap = (const float4*)(Ab + (size_t)lrow[j] * K + lg[j] * 8);
            float4 x0 = ap[0], x1 = ap[1];
            float xs[8] = {x0.x, x0.y, x0.z, x0.w, x1.x, x1.y, x1.z, x1.w};
            uint32_t hw[4], lw[4];
#pragma unroll
            for (int i = 0; i < 4; i++) {
                __nv_bfloat16 h0 = __float2bfloat16(xs[2*i]);
                __nv_bfloat16 h1 = __float2bfloat16(xs[2*i+1]);
                __nv_bfloat16 l0 = __float2bfloat16(xs[2*i]   - __bfloat162float(h0));
                __nv_bfloat16 l1 = __float2bfloat16(xs[2*i+1] - __bfloat162float(h1));
                hw[i] = (uint32_t)__bfloat16_as_ushort(h0) | ((uint32_t)__bfloat16_as_ushort(h1) << 16);
                lw[i] = (uint32_t)__bfloat16_as_ushort(l0) | ((uint32_t)__bfloat16_as_ushort(l1) << 16);
            }
            uint32_t sw = SWZ128((uint32_t)(lrow[j] * 128 + lg[j] * 16));
            *(uint4*)(smem + AH_OFF + sw) = make_uint4(hw[0], hw[1], hw[2], hw[3]);
            *(uint4*)(smem + AL_OFF + sw) = make_uint4(lw[0], lw[1], lw[2], lw[3]);
        }
        CP_WAIT0();
        __syncthreads();
    }

    // ---- main loop ----
    for (int c = 0; c < nchunks; c++) {
        const int p = c & 1;
        const uint32_t bufp = sb + p * BUF_STRIDE;
        const bool has_next = (c + 1) < nchunks;
        const uint32_t bufn = sb + (p ^ 1) * BUF_STRIDE;
        char* bufn_c = smem + (p ^ 1) * BUF_STRIDE;

        float4 st[4][2];
        if (has_next) {
            const int cc = (c + 1) * 64;
#pragma unroll
            for (int j = 0; j < 4; j++) {
                uint32_t sw = SWZ128((uint32_t)(lrow[j] * 128 + lg[j] * 16));
                CP_ASYNC16(bufn + BH_OFF + sw, (const char*)(Bh + (size_t)lrow[j] * K + cc + lg[j] * 8));
                CP_ASYNC16(bufn + BL_OFF + sw, (const char*)(Bl + (size_t)lrow[j] * K + cc + lg[j] * 8));
            }
            CP_COMMIT();
#pragma unroll
            for (int j = 0; j < 4; j++) {
                const float4* ap = (const float4*)(Ab + (size_t)lrow[j] * K + cc + lg[j] * 8);
                st[j][0] = ap[0];
                st[j][1] = ap[1];
            }
        }

        // --- MMA over buffer p: 4 k-steps x (hi*hi + hi*lo + lo*hi) ---
#pragma unroll
        for (int ks = 0; ks < 4; ks++) {
            const int krow = lane & 15;
            const int kcB  = (ks * 16 + (lane >> 4) * 8) * 2;   // byte col offset
            uint32_t ah[2][4], al[2][4];
#pragma unroll
            for (int mt = 0; mt < 2; mt++) {
                uint32_t off = (uint32_t)((wm * 32 + mt * 16 + krow) * 128) + kcB;
                ldsm_x4(ah[mt], bufp + AH_OFF + SWZ128(off));
                ldsm_x4(al[mt], bufp + AL_OFF + SWZ128(off));
            }
            uint32_t bh[8][2], bl[8][2];
#pragma unroll
            for (int bt = 0; bt < 4; bt++) {
                uint32_t off = (uint32_t)((wn * 64 + bt * 16 + krow) * 128) + kcB;
                uint32_t r[4], r2[4];
                ldsm_x4(r,  bufp + BH_OFF + SWZ128(off));
                ldsm_x4(r2, bufp + BL_OFF + SWZ128(off));
                bh[2*bt][0] = r[0];  bh[2*bt+1][0] = r[1];
                bh[2*bt][1] = r[2];  bh[2*bt+1][1] = r[3];
                bl[2*bt][0] = r2[0]; bl[2*bt+1][0] = r2[1];
                bl[2*bt][1] = r2[2]; bl[2*bt+1][1] = r2[3];
            }
#pragma unroll
            for (int mt = 0; mt < 2; mt++)
#pragma unroll
                for (int nt = 0; nt < 8; nt++) {
                    mma_bf16(acc[mt][nt], ah[mt], bh[nt][0], bh[nt][1]);
                    mma_bf16(acc[mt][nt], ah[mt], bl[nt][0], bl[nt][1]);
                    mma_bf16(acc[mt][nt], al[mt], bh[nt][0], bh[nt][1]);
                }
        }

        if (has_next) {
#pragma unroll
            for (int j = 0; j < 4; j++) {
                float xs[8] = {st[j][0].x, st[j][0].y, st[j][0].z, st[j][0].w,
                               st[j][1].x, st[j][1].y, st[j][1].z, st[j][1].w};
                uint32_t hw[4], lw[4];
#pragma unroll
                for (int i = 0; i < 4; i++) {
                    __nv_bfloat16 h0 = __float2bfloat16(xs[2*i]);
                    __nv_bfloat16 h1 = __float2bfloat16(xs[2*i+1]);
                    __nv_bfloat16 l0 = __float2bfloat16(xs[2*i]   - __bfloat162float(h0));
                    __nv_bfloat16 l1 = __float2bfloat16(xs[2*i+1] - __bfloat162float(h1));
                    hw[i] = (uint32_t)__bfloat16_as_ushort(h0) | ((uint32_t)__bfloat16_as_ushort(h1) << 16);
                    lw[i] = (uint32_t)__bfloat16_as_ushort(l0) | ((uint32_t)__bfloat16_as_ushort(l1) << 16);
                }
                uint32_t sw = SWZ128((uint32_t)(lrow[j] * 128 + lg[j] * 16));
                *(uint4*)(bufn_c + AH_OFF + sw) = make_uint4(hw[0], hw[1], hw[2], hw[3]);
                *(uint4*)(bufn_c + AL_OFF + sw) = make_uint4(lw[0], lw[1], lw[2], lw[3]);
            }
            CP_WAIT0();
        }
        __syncthreads();
    }

    // ---- epilogue: bias + ReLU, direct stores ----
    const int rbase = mb * 128 + wm * 32 + (lane >> 2);
    const int cbase = nb * 128 + wn * 64 + 2 * (lane & 3);
#pragma unroll
    for (int mt = 0; mt < 2; mt++)
#pragma unroll
        for (int nt = 0; nt < 8; nt++) {
            int r0 = rbase + mt * 16;
            int c0 = cbase + nt * 8;
            float b0v = bias[c0], b1v = bias[c0 + 1];
            float2 v0, v1;
            v0.x = fmaxf(acc[mt][nt][0] + b0v, 0.f);
            v0.y = fmaxf(acc[mt][nt][1] + b1v, 0.f);
            v1.x = fmaxf(acc[mt][nt][2] + b0v, 0.f);
            v1.y = fmaxf(acc[mt][nt][3] + b1v, 0.f);
            *(float2*)(C + (size_t)r0 * HDIM + c0)       = v0;
            *(float2*)(C + (size_t)(r0 + 8) * HDIM + c0) = v1;
        }
}

// ---------------------------------------------------------------------------
// kernel_launch
// ---------------------------------------------------------------------------
extern "C" void kernel_launch(void* const* d_in, const int* in_sizes, int n_in,
                              void* d_out, int out_size) {
    const float* anchor = (const float*)d_in[0];
    const float* rnd    = (const float*)d_in[1];
    const void*  mask   = d_in[2];
    const float* enc_w0 = (const float*)d_in[3];
    const float* enc_b0 = (const float*)d_in[4];
    const float* enc_w  = (const float*)d_in[5];
    const float* enc_b  = (const float*)d_in[6];
    const float* head_w = (const float*)d_in[7];
    const float* head_b = (const float*)d_in[8];
    float* out = (float*)d_out;

    float *X, *A0, *A1;
    __nv_bfloat16 *Whi, *Wlo;
    cudaGetSymbolAddress((void**)&X,   g_X);
    cudaGetSymbolAddress((void**)&A0,  g_A0);
    cudaGetSymbolAddress((void**)&A1,  g_A1);
    cudaGetSymbolAddress((void**)&Whi, g_Whi);
    cudaGetSymbolAddress((void**)&Wlo, g_Wlo);

    cudaFuncSetAttribute(gemm_hmma, cudaFuncAttributeMaxDynamicSharedMemorySize, SM_TOTAL);

    detect_mask_kernel<<<1, 256>>>((const unsigned char*)mask);
    const int nSel = BATCH * MDIM;
    build_x_kernel<<<(nSel + 255) / 256, 256>>>(anchor, rnd, mask);

    const size_t HH = (size_t)HDIM * HDIM;
    const size_t woff[6] = {0, 524288, 524288 + HH, 524288 + 2*HH, 524288 + 3*HH, 524288 + 4*HH};
    dim3 wb(32, 8);
    wsplit_kernel<<<dim3(HDIM/32, MDIM/32), wb>>>(enc_w0,        Whi + woff[0], Wlo + woff[0], MDIM, HDIM);
    wsplit_kernel<<<dim3(HDIM/32, HDIM/32), wb>>>(enc_w  + 0*HH, Whi + woff[1], Wlo + woff[1], HDIM, HDIM);
    wsplit_kernel<<<dim3(HDIM/32, HDIM/32), wb>>>(enc_w  + 1*HH, Whi + woff[2], Wlo + woff[2], HDIM, HDIM);
    wsplit_kernel<<<dim3(HDIM/32, HDIM/32), wb>>>(enc_w  + 2*HH, Whi + woff[3], Wlo + woff[3], HDIM, HDIM);
    wsplit_kernel<<<dim3(HDIM/32, HDIM/32), wb>>>(head_w + 0*HH, Whi + woff[4], Wlo + woff[4], HDIM, HDIM);
    wsplit_kernel<<<dim3(HDIM/32, HDIM/32), wb>>>(head_w + 1*HH, Whi + woff[5], Wlo + woff[5], HDIM, HDIM);

    dim3 grid(HDIM / 128, ROWS / 128);   // (8, 128)
    gemm_hmma<<<grid, 256, SM_TOTAL>>>(X,  Whi + woff[0], Wlo + woff[0], enc_b0,          A0,  MDIM);
    gemm_hmma<<<grid, 256, SM_TOTAL>>>(A0, Whi + woff[1], Wlo + woff[1], enc_b + 0*HDIM,  A1,  HDIM);
    gemm_hmma<<<grid, 256, SM_TOTAL>>>(A1, Whi + woff[2], Wlo + woff[2], enc_b + 1*HDIM,  A0,  HDIM);
    gemm_hmma<<<grid, 256, SM_TOTAL>>>(A0, Whi + woff[3], Wlo + woff[3], enc_b + 2*HDIM,  A1,  HDIM);
    gemm_hmma<<<grid, 256, SM_TOTAL>>>(A1, Whi + woff[4], Wlo + woff[4], head_b + 0*HDIM, A0,  HDIM);
    gemm_hmma<<<grid, 256, SM_TOTAL>>>(A0, Whi + woff[5], Wlo + woff[5], head_b + 1*HDIM, out, HDIM);
}

// round 5
// speedup vs baseline: 2.3988x; 1.1420x over previous
#include <cuda_runtime.h>
#include <cuda_bf16.h>
#include <cstdint>

#define BATCH   8192
#define MDIM    512
#define HDIM    1024
#define ROWS    (2 * BATCH)          // 16384 stacked rows (anchor ; positive)

// ---------------------------------------------------------------------------
// Device scratch (no allocations allowed) — all activations live as bf16 hi/lo
// ---------------------------------------------------------------------------
__device__ __align__(256) __nv_bfloat16 g_Xhi [(size_t)ROWS * MDIM];  // 16 MB
__device__ __align__(256) __nv_bfloat16 g_Xlo [(size_t)ROWS * MDIM];
__device__ __align__(256) __nv_bfloat16 g_A0hi[(size_t)ROWS * HDIM];  // 32 MB
__device__ __align__(256) __nv_bfloat16 g_A0lo[(size_t)ROWS * HDIM];
__device__ __align__(256) __nv_bfloat16 g_A1hi[(size_t)ROWS * HDIM];
__device__ __align__(256) __nv_bfloat16 g_A1lo[(size_t)ROWS * HDIM];
#define WTOTAL 5767168   // 512*1024 + 5*1024*1024
__device__ __align__(256) __nv_bfloat16 g_Whi[WTOTAL];
__device__ __align__(256) __nv_bfloat16 g_Wlo[WTOTAL];
__device__ int g_mask_byte_flag;

// ---------------------------------------------------------------------------
// Helpers (compute_103-legal: ldmatrix / mma.sync / cp.async)
// ---------------------------------------------------------------------------
__device__ __forceinline__ uint32_t smem_u32(const void* p) {
    uint32_t a;
    asm("{ .reg .u64 t; cvta.to.shared.u64 t, %1; cvt.u32.u64 %0, t; }" : "=r"(a) : "l"(p));
    return a;
}
__device__ __forceinline__ void ldsm_x4(uint32_t (&r)[4], uint32_t a) {
    asm volatile("ldmatrix.sync.aligned.m8n8.x4.shared.b16 {%0,%1,%2,%3}, [%4];"
                 : "=r"(r[0]), "=r"(r[1]), "=r"(r[2]), "=r"(r[3]) : "r"(a));
}
__device__ __forceinline__ void mma_bf16(float (&d)[4], const uint32_t (&a)[4],
                                         uint32_t b0, uint32_t b1) {
    asm volatile("mma.sync.aligned.m16n8k16.row.col.f32.bf16.bf16.f32 "
                 "{%0,%1,%2,%3}, {%4,%5,%6,%7}, {%8,%9}, {%0,%1,%2,%3};"
                 : "+f"(d[0]), "+f"(d[1]), "+f"(d[2]), "+f"(d[3])
                 : "r"(a[0]), "r"(a[1]), "r"(a[2]), "r"(a[3]), "r"(b0), "r"(b1));
}
#define CP_ASYNC16(dst, src) \
    asm volatile("cp.async.cg.shared.global [%0], [%1], 16;" :: "r"(dst), "l"(src))
#define CP_COMMIT()  asm volatile("cp.async.commit_group;" ::: "memory")
#define CP_WAIT1()   asm volatile("cp.async.wait_group 1;" ::: "memory")
#define SWZ128(o) ((o) ^ (((o) >> 3) & 0x70))

// ---------------------------------------------------------------------------
// Mask dtype detection + split input build
// ---------------------------------------------------------------------------
__global__ void detect_mask_kernel(const unsigned char* __restrict__ m) {
    __shared__ int s_gt1, s_odd;
    if (threadIdx.x == 0) { s_gt1 = 0; s_odd = 0; }
    __syncthreads();
    int gt1 = 0, odd = 0;
    for (int o = threadIdx.x; o < 65536; o += blockDim.x) {
        unsigned char b = m[o];
        if (b > 1) gt1 = 1;
        if ((o & 3) && b) odd = 1;
    }
    if (gt1) atomicOr(&s_gt1, 1);
    if (odd) atomicOr(&s_odd, 1);
    __syncthreads();
    if (threadIdx.x == 0) g_mask_byte_flag = (!s_gt1 && s_odd) ? 1 : 0;
}

__device__ __forceinline__ void split_store(__nv_bfloat16* hi, __nv_bfloat16* lo,
                                            size_t idx, float v) {
    __nv_bfloat16 h = __float2bfloat16(v);
    hi[idx] = h;
    lo[idx] = __float2bfloat16(v - __bfloat162float(h));
}

__global__ void build_x_kernel(const float* __restrict__ anchor,
                               const float* __restrict__ rnd,
                               const void*  __restrict__ mask) {
    int i = blockIdx.x * blockDim.x + threadIdx.x;
    const int n = BATCH * MDIM;
    if (i >= n) return;
    float a = anchor[i];
    split_store(g_Xhi, g_Xlo, i, a);
    bool m;
    if (g_mask_byte_flag) m = ((const unsigned char*)mask)[i] != 0;
    else                  m = ((const unsigned int*)mask)[i] != 0u;
    split_store(g_Xhi, g_Xlo, (size_t)n + i, m ? rnd[i] : a);
}

// ---------------------------------------------------------------------------
// Weight transpose + bf16 split:  W[K,N] f32 -> hi/lo [N,K] bf16
// ---------------------------------------------------------------------------
__global__ void wsplit_kernel(const float* __restrict__ W,
                              __nv_bfloat16* __restrict__ hi,
                              __nv_bfloat16* __restrict__ lo,
                              int K, int N) {
    __shared__ float t[32][33];
    int nb = blockIdx.x * 32, kb = blockIdx.y * 32;
    int tx = threadIdx.x, ty = threadIdx.y;   // (32, 8)
    for (int r = ty; r < 32; r += 8)
        t[r][tx] = W[(size_t)(kb + r) * N + nb + tx];
    __syncthreads();
    for (int r = ty; r < 32; r += 8) {
        float v = t[tx][r];
        __nv_bfloat16 h = __float2bfloat16(v);
        __nv_bfloat16 l = __float2bfloat16(v - __bfloat162float(h));
        size_t o = (size_t)(nb + r) * K + kb + tx;
        hi[o] = h;  lo[o] = l;
    }
}

// ---------------------------------------------------------------------------
// HMMA GEMM, all-async operands, 3-stage cp.async pipeline.
//   acc = Ah@Bh + Ah@Bl + Al@Bh  (fp32 TC accumulate)
//   CTA 128x128, BK=64, 8 warps (warp tile 32x64).
//   Epilogue: relu(acc+bias) -> either split bf16 hi/lo planes, or fp32 out.
// SMEM stage s at s*65536: Ah(16K) Al(16K) Bh(16K) Bl(16K); 3 stages = 192KB.
// ---------------------------------------------------------------------------
#define AH_OFF 0
#define AL_OFF 16384
#define BH_OFF 32768
#define BL_OFF 49152
#define STAGE_STRIDE 65536
#define SM_TOTAL (3 * STAGE_STRIDE)

__global__ void __launch_bounds__(256, 1)
gemm_hmma(const __nv_bfloat16* __restrict__ Ahi,
          const __nv_bfloat16* __restrict__ Alo,
          const __nv_bfloat16* __restrict__ Bhi,
          const __nv_bfloat16* __restrict__ Blo,
          const float* __restrict__ bias,
          __nv_bfloat16* __restrict__ Chi,
          __nv_bfloat16* __restrict__ Clo,
          float* __restrict__ Cf32,
          int K, int writeF32) {
    extern __shared__ char smem[];
    const uint32_t sb = smem_u32(smem);
    const int tid  = threadIdx.x;
    const int wid  = tid >> 5, lane = tid & 31;
    const int wm   = wid & 3;          // warp m (4)
    const int wn   = wid >> 2;         // warp n (2)
    const int mb   = blockIdx.y, nb = blockIdx.x;

    const __nv_bfloat16* Ah = Ahi + (size_t)mb * 128 * K;
    const __nv_bfloat16* Al = Alo + (size_t)mb * 128 * K;
    const __nv_bfloat16* Bh = Bhi + (size_t)nb * 128 * K;
    const __nv_bfloat16* Bl = Blo + (size_t)nb * 128 * K;

    // loader mapping: seg = tid + 256*j (j<4): row = seg>>3 (0..127), g = seg&7
    const int g8   = (tid & 7) * 8;                 // bf16 col within 64-chunk
    const uint32_t swz[4] = {
        SWZ128((uint32_t)(((tid + 0)   >> 3) * 128 + (tid & 7) * 16)),
        SWZ128((uint32_t)(((tid + 256) >> 3) * 128 + (tid & 7) * 16)),
        SWZ128((uint32_t)(((tid + 512) >> 3) * 128 + (tid & 7) * 16)),
        SWZ128((uint32_t)(((tid + 768) >> 3) * 128 + (tid & 7) * 16)) };
    const size_t rowK[4] = {
        (size_t)((tid + 0)   >> 3) * K, (size_t)((tid + 256) >> 3) * K,
        (size_t)((tid + 512) >> 3) * K, (size_t)((tid + 768) >> 3) * K };

    float acc[2][8][4];
#pragma unroll
    for (int mt = 0; mt < 2; mt++)
#pragma unroll
        for (int nt = 0; nt < 8; nt++)
#pragma unroll
            for (int q = 0; q < 4; q++) acc[mt][nt][q] = 0.f;

    const int nchunks = K >> 6;

    // issue one stage of loads
    auto issue_stage = [&](int c, int s) {
        const uint32_t bs = sb + s * STAGE_STRIDE;
        const int cc = c * 64 + g8;
#pragma unroll
        for (int j = 0; j < 4; j++) {
            CP_ASYNC16(bs + AH_OFF + swz[j], (const char*)(Ah + rowK[j] + cc));
            CP_ASYNC16(bs + AL_OFF + swz[j], (const char*)(Al + rowK[j] + cc));
            CP_ASYNC16(bs + BH_OFF + swz[j], (const char*)(Bh + rowK[j] + cc));
            CP_ASYNC16(bs + BL_OFF + swz[j], (const char*)(Bl + rowK[j] + cc));
        }
    };

    // prologue: stages 0 and 1 in flight
    issue_stage(0, 0); CP_COMMIT();
    issue_stage(1, 1); CP_COMMIT();

    for (int c = 0; c < nchunks; c++) {
        CP_WAIT1();              // group c complete (c+1 may be pending)
        __syncthreads();         // all warps done with stage (c-1) reads

        if (c + 2 < nchunks) issue_stage(c + 2, (c + 2) % 3);
        CP_COMMIT();             // keep one group per iteration

        const uint32_t bufp = sb + (c % 3) * STAGE_STRIDE;
#pragma unroll
        for (int ks = 0; ks < 4; ks++) {
            const int krow = lane & 15;
            const int kcB  = (ks * 16 + (lane >> 4) * 8) * 2;
            uint32_t ah[2][4], al[2][4];
#pragma unroll
            for (int mt = 0; mt < 2; mt++) {
                uint32_t off = (uint32_t)((wm * 32 + mt * 16 + krow) * 128) + kcB;
                ldsm_x4(ah[mt], bufp + AH_OFF + SWZ128(off));
                ldsm_x4(al[mt], bufp + AL_OFF + SWZ128(off));
            }
            uint32_t bh[8][2], bl[8][2];
#pragma unroll
            for (int bt = 0; bt < 4; bt++) {
                uint32_t off = (uint32_t)((wn * 64 + bt * 16 + krow) * 128) + kcB;
                uint32_t r[4], r2[4];
                ldsm_x4(r,  bufp + BH_OFF + SWZ128(off));
                ldsm_x4(r2, bufp + BL_OFF + SWZ128(off));
                bh[2*bt][0] = r[0];  bh[2*bt+1][0] = r[1];
                bh[2*bt][1] = r[2];  bh[2*bt+1][1] = r[3];
                bl[2*bt][0] = r2[0]; bl[2*bt+1][0] = r2[1];
                bl[2*bt][1] = r2[2]; bl[2*bt+1][1] = r2[3];
            }
#pragma unroll
            for (int mt = 0; mt < 2; mt++)
#pragma unroll
                for (int nt = 0; nt < 8; nt++) {
                    mma_bf16(acc[mt][nt], ah[mt], bh[nt][0], bh[nt][1]);
                    mma_bf16(acc[mt][nt], ah[mt], bl[nt][0], bl[nt][1]);
                    mma_bf16(acc[mt][nt], al[mt], bh[nt][0], bh[nt][1]);
                }
        }
    }

    // ---- epilogue: relu(acc+bias); write split bf16 planes or fp32 ----
    const int rbase = mb * 128 + wm * 32 + (lane >> 2);
    const int cbase = nb * 128 + wn * 64 + 2 * (lane & 3);
#pragma unroll
    for (int mt = 0; mt < 2; mt++)
#pragma unroll
        for (int nt = 0; nt < 8; nt++) {
            const int c0 = cbase + nt * 8;
            const float b0v = bias[c0], b1v = bias[c0 + 1];
            float v00 = fmaxf(acc[mt][nt][0] + b0v, 0.f);
            float v01 = fmaxf(acc[mt][nt][1] + b1v, 0.f);
            float v10 = fmaxf(acc[mt][nt][2] + b0v, 0.f);
            float v11 = fmaxf(acc[mt][nt][3] + b1v, 0.f);
            const size_t o0 = (size_t)(rbase + mt * 16)     * HDIM + c0;
            const size_t o1 = (size_t)(rbase + mt * 16 + 8) * HDIM + c0;
            if (writeF32) {
                *(float2*)(Cf32 + o0) = make_float2(v00, v01);
                *(float2*)(Cf32 + o1) = make_float2(v10, v11);
            } else {
                __nv_bfloat16 h00 = __float2bfloat16(v00);
                __nv_bfloat16 h01 = __float2bfloat16(v01);
                __nv_bfloat16 h10 = __float2bfloat16(v10);
                __nv_bfloat16 h11 = __float2bfloat16(v11);
                __nv_bfloat162 l0, l1;
                l0.x = __float2bfloat16(v00 - __bfloat162float(h00));
                l0.y = __float2bfloat16(v01 - __bfloat162float(h01));
                l1.x = __float2bfloat16(v10 - __bfloat162float(h10));
                l1.y = __float2bfloat16(v11 - __bfloat162float(h11));
                *(__nv_bfloat162*)(Chi + o0) = make_bfloat162(h00, h01);
                *(__nv_bfloat162*)(Chi + o1) = make_bfloat162(h10, h11);
                *(__nv_bfloat162*)(Clo + o0) = l0;
                *(__nv_bfloat162*)(Clo + o1) = l1;
            }
        }
}

// ---------------------------------------------------------------------------
// kernel_launch
// ---------------------------------------------------------------------------
extern "C" void kernel_launch(void* const* d_in, const int* in_sizes, int n_in,
                              void* d_out, int out_size) {
    const float* anchor = (const float*)d_in[0];
    const float* rnd    = (const float*)d_in[1];
    const void*  mask   = d_in[2];
    const float* enc_w0 = (const float*)d_in[3];
    const float* enc_b0 = (const float*)d_in[4];
    const float* enc_w  = (const float*)d_in[5];
    const float* enc_b  = (const float*)d_in[6];
    const float* head_w = (const float*)d_in[7];
    const float* head_b = (const float*)d_in[8];
    float* out = (float*)d_out;

    __nv_bfloat16 *Xhi, *Xlo, *A0hi, *A0lo, *A1hi, *A1lo, *Whi, *Wlo;
    cudaGetSymbolAddress((void**)&Xhi,  g_Xhi);
    cudaGetSymbolAddress((void**)&Xlo,  g_Xlo);
    cudaGetSymbolAddress((void**)&A0hi, g_A0hi);
    cudaGetSymbolAddress((void**)&A0lo, g_A0lo);
    cudaGetSymbolAddress((void**)&A1hi, g_A1hi);
    cudaGetSymbolAddress((void**)&A1lo, g_A1lo);
    cudaGetSymbolAddress((void**)&Whi,  g_Whi);
    cudaGetSymbolAddress((void**)&Wlo,  g_Wlo);

    cudaFuncSetAttribute(gemm_hmma, cudaFuncAttributeMaxDynamicSharedMemorySize, SM_TOTAL);

    detect_mask_kernel<<<1, 256>>>((const unsigned char*)mask);
    const int nSel = BATCH * MDIM;
    build_x_kernel<<<(nSel + 255) / 256, 256>>>(anchor, rnd, mask);

    const size_t HH = (size_t)HDIM * HDIM;
    const size_t woff[6] = {0, 524288, 524288 + HH, 524288 + 2*HH, 524288 + 3*HH, 524288 + 4*HH};
    dim3 wb(32, 8);
    wsplit_kernel<<<dim3(HDIM/32, MDIM/32), wb>>>(enc_w0,        Whi + woff[0], Wlo + woff[0], MDIM, HDIM);
    wsplit_kernel<<<dim3(HDIM/32, HDIM/32), wb>>>(enc_w  + 0*HH, Whi + woff[1], Wlo + woff[1], HDIM, HDIM);
    wsplit_kernel<<<dim3(HDIM/32, HDIM/32), wb>>>(enc_w  + 1*HH, Whi + woff[2], Wlo + woff[2], HDIM, HDIM);
    wsplit_kernel<<<dim3(HDIM/32, HDIM/32), wb>>>(enc_w  + 2*HH, Whi + woff[3], Wlo + woff[3], HDIM, HDIM);
    wsplit_kernel<<<dim3(HDIM/32, HDIM/32), wb>>>(head_w + 0*HH, Whi + woff[4], Wlo + woff[4], HDIM, HDIM);
    wsplit_kernel<<<dim3(HDIM/32, HDIM/32), wb>>>(head_w + 1*HH, Whi + woff[5], Wlo + woff[5], HDIM, HDIM);

    dim3 grid(HDIM / 128, ROWS / 128);   // (8, 128)
    gemm_hmma<<<grid, 256, SM_TOTAL>>>(Xhi,  Xlo,  Whi + woff[0], Wlo + woff[0], enc_b0,          A0hi, A0lo, nullptr, MDIM, 0);
    gemm_hmma<<<grid, 256, SM_TOTAL>>>(A0hi, A0lo, Whi + woff[1], Wlo + woff[1], enc_b + 0*HDIM,  A1hi, A1lo, nullptr, HDIM, 0);
    gemm_hmma<<<grid, 256, SM_TOTAL>>>(A1hi, A1lo, Whi + woff[2], Wlo + woff[2], enc_b + 1*HDIM,  A0hi, A0lo, nullptr, HDIM, 0);
    gemm_hmma<<<grid, 256, SM_TOTAL>>>(A0hi, A0lo, Whi + woff[3], Wlo + woff[3], enc_b + 2*HDIM,  A1hi, A1lo, nullptr, HDIM, 0);
    gemm_hmma<<<grid, 256, SM_TOTAL>>>(A1hi, A1lo, Whi + woff[4], Wlo + woff[4], head_b + 0*HDIM, A0hi, A0lo, nullptr, HDIM, 0);
    gemm_hmma<<<grid, 256, SM_TOTAL>>>(A0hi, A0lo, Whi + woff[5], Wlo + woff[5], head_b + 1*HDIM, nullptr, nullptr, out, HDIM, 1);
}